// round 2
// baseline (speedup 1.0000x reference)
#include <cuda_runtime.h>

#define HW 4096  // 64*64

// Intermediate buffers (device globals: no allocation allowed in kernel_launch)
__device__ float g_act[4 * 64 * HW];        // [b][co=64][h][w], post BN+SiLU
__device__ float g_mask[4 * HW * 100];      // [b][pixel][s=4][k=25], softmaxed

// ---------------------------------------------------------------------------
// Kernel A: 1x1 compression conv (256->64) + BatchNorm(eval) + SiLU
// act[b, o, p] = silu( (sum_c w[o,c]*x[b,c,p]) * inv[o] + off[o] )
// Block: 64 pixels x 64 outputs.  256 threads, thread tile 4o x 4p.
// ---------------------------------------------------------------------------
__global__ void __launch_bounds__(256) kA(
    const float* __restrict__ x, const float* __restrict__ wc,
    const float* __restrict__ gma, const float* __restrict__ bet,
    const float* __restrict__ mea, const float* __restrict__ var) {
  extern __shared__ float sm[];
  float* xs = sm;               // [256][64]
  float* ws = sm + 256 * 64;    // [256][68] (transposed w, padded stride)

  int blk = blockIdx.x;         // 0..255
  int b = blk >> 6;
  int p0 = (blk & 63) << 6;
  int tid = threadIdx.x;

  const float* xb = x + (size_t)b * 256 * HW + p0;
  for (int idx = tid; idx < 256 * 64; idx += 256) {
    int c = idx >> 6, p = idx & 63;
    xs[idx] = xb[(size_t)c * HW + p];
  }
  for (int idx = tid; idx < 256 * 64; idx += 256) {
    int c = idx & 255, o = idx >> 8;
    ws[c * 68 + o] = wc[o * 256 + c];
  }
  __syncthreads();

  int pp = tid & 15;   // pixel group
  int po = tid >> 4;   // output group
  float acc[4][4] = {};

  const float* xp = xs + pp * 4;
  const float* wp = ws + po * 4;
#pragma unroll 4
  for (int c = 0; c < 256; c++) {
    float4 xv = *(const float4*)(xp + c * 64);
    float4 wv = *(const float4*)(wp + c * 68);
    float xa[4] = {xv.x, xv.y, xv.z, xv.w};
    float wa[4] = {wv.x, wv.y, wv.z, wv.w};
#pragma unroll
    for (int oo = 0; oo < 4; oo++)
#pragma unroll
      for (int pz = 0; pz < 4; pz++)
        acc[oo][pz] += wa[oo] * xa[pz];
  }

  float* actb = g_act + (size_t)b * 64 * HW + p0 + pp * 4;
#pragma unroll
  for (int oo = 0; oo < 4; oo++) {
    int o = po * 4 + oo;
    float inv = gma[o] * rsqrtf(var[o] + 1e-5f);
    float off = bet[o] - mea[o] * inv;
    float4 r;
    float v;
    v = acc[oo][0] * inv + off; r.x = v / (1.f + __expf(-v));
    v = acc[oo][1] * inv + off; r.y = v / (1.f + __expf(-v));
    v = acc[oo][2] * inv + off; r.z = v / (1.f + __expf(-v));
    v = acc[oo][3] * inv + off; r.w = v / (1.f + __expf(-v));
    *(float4*)(actb + (size_t)o * HW) = r;
  }
}

// ---------------------------------------------------------------------------
// Kernel B: 3x3 conv (64 -> 100 channels, pad 1) + softmax over k (per s)
// Channel o = k*4 + s; softmax over k=0..24 for each s=0..3 is per-thread.
// Block: 8x8 pixel tile. 128 threads = 32 pixel-slots x 4 s.
// Each thread: 2 pixels (rows ty and ty+4), 25 k-accumulators each.
// Weights staged in smem transposed [ci_l*9 + r][o], 16-ci chunks.
// ---------------------------------------------------------------------------
__device__ __forceinline__ void softmax25_store(float* acc, float* dst) {
  float m = acc[0];
#pragma unroll
  for (int k = 1; k < 25; k++) m = fmaxf(m, acc[k]);
  float ssum = 0.f;
#pragma unroll
  for (int k = 0; k < 25; k++) { acc[k] = __expf(acc[k] - m); ssum += acc[k]; }
  float rs = 1.f / ssum;
#pragma unroll
  for (int k = 0; k < 25; k++) dst[k] = acc[k] * rs;
}

__global__ void __launch_bounds__(128) kB(const float* __restrict__ we) {
  extern __shared__ float sm[];
  float* as_ = sm;            // act tile: [64][10][10] = 6400
  float* ws = sm + 6400;      // w chunk:  [144][101]   = 14544

  int b = blockIdx.z;
  int i0 = blockIdx.y << 3, j0 = blockIdx.x << 3;
  int tid = threadIdx.x;
  int s = tid & 3, q = tid >> 2;   // q in 0..31
  int ty = q >> 3, tx = q & 7;     // pixel0 (ty,tx), pixel1 (ty+4,tx)

  // Load act tile with halo (pad 1), zero outside
  for (int idx = tid; idx < 6400; idx += 128) {
    int ci = idx / 100;
    int rem = idx - ci * 100;
    int rr = rem / 10, cc2 = rem - rr * 10;
    int gi = i0 + rr - 1, gj = j0 + cc2 - 1;
    float v = 0.f;
    if ((unsigned)gi < 64u && (unsigned)gj < 64u)
      v = g_act[((size_t)(b * 64 + ci)) * HW + (gi << 6) + gj];
    as_[idx] = v;
  }

  float acc0[25] = {}, acc1[25] = {};

#pragma unroll 1
  for (int cc = 0; cc < 4; cc++) {   // ci chunks of 16
    __syncthreads();
    for (int idx = tid; idx < 14400; idx += 128) {
      int o = idx / 144;
      int t = idx - o * 144;
      ws[t * 101 + o] = we[o * 576 + cc * 144 + t];
    }
    __syncthreads();
#pragma unroll 1
    for (int cl = 0; cl < 16; cl++) {
      const float* ap = as_ + (cc * 16 + cl) * 100;
#pragma unroll
      for (int dy = 0; dy < 3; dy++) {
#pragma unroll
        for (int dx = 0; dx < 3; dx++) {
          float a0 = ap[(ty + dy) * 10 + tx + dx];
          float a1 = ap[(ty + 4 + dy) * 10 + tx + dx];
          const float* wp = ws + (cl * 9 + dy * 3 + dx) * 101 + s;
#pragma unroll
          for (int k = 0; k < 25; k++) {
            float wv = wp[k << 2];   // w[o = k*4 + s]
            acc0[k] += wv * a0;
            acc1[k] += wv * a1;
          }
        }
      }
    }
  }

  int p0 = (i0 + ty) * 64 + (j0 + tx);
  int p1 = p0 + 256;   // row +4
  softmax25_store(acc0, g_mask + ((size_t)(b * HW + p0)) * 100 + s * 25);
  softmax25_store(acc1, g_mask + ((size_t)(b * HW + p1)) * 100 + s * 25);
}

// ---------------------------------------------------------------------------
// Kernel C: 5x5 unfold + mask-weighted sum + pixel shuffle (x2 upsample)
// out[b, c, 2i+s0, 2j+s1] = sum_k mask[b,k,s0*2+s1,i,j] * xpad[b,c,i+dy-2,j+dx-2]
// Block: (b, row pair ri -> rows 2ri,2ri+1, 64-channel chunk). 128 threads,
// thread = (r in {0,1}, j in 0..63). 100 mask values cached in registers,
// reused across all 64 channels.
// ---------------------------------------------------------------------------
__global__ void __launch_bounds__(128) kC(const float* __restrict__ x,
                                          float* __restrict__ out) {
  extern __shared__ float xs[];   // [64][6][68]
  int gc0 = blockIdx.x << 6;
  int ri = blockIdx.y;
  int b = blockIdx.z;
  int tid = threadIdx.x;
  int r = tid >> 6, j = tid & 63;
  int i = (ri << 1) + r;

  for (int idx = tid; idx < 64 * 6 * 68; idx += 128) xs[idx] = 0.f;
  __syncthreads();
  for (int idx = tid; idx < 64 * 6 * 64; idx += 128) {
    int c = idx / 384;
    int rem = idx - c * 384;
    int lr = rem >> 6, col = rem & 63;
    int grow = (ri << 1) - 2 + lr;
    if ((unsigned)grow < 64u)
      xs[c * 408 + lr * 68 + col + 2] =
          x[((size_t)(b * 256 + gc0 + c)) * HW + (grow << 6) + col];
  }
  __syncthreads();

  // Mask for this pixel -> registers (layout: linear index = s*25 + k)
  float mk[100];
  const float4* mp =
      (const float4*)(g_mask + ((size_t)(b * HW + (i << 6) + j)) * 100);
#pragma unroll
  for (int t = 0; t < 25; t++) {
    float4 v = mp[t];
    mk[4 * t] = v.x; mk[4 * t + 1] = v.y; mk[4 * t + 2] = v.z; mk[4 * t + 3] = v.w;
  }

  const float* pbase = xs + r * 68 + j;
  float* ob = out + ((size_t)(b * 256 + gc0) * 128 + (i << 1)) * 128 + (j << 1);

#pragma unroll 1
  for (int c = 0; c < 64; c++) {
    const float* pp_ = pbase + c * 408;
    float a0 = 0.f, a1 = 0.f, a2 = 0.f, a3 = 0.f;
#pragma unroll
    for (int dy = 0; dy < 5; dy++) {
#pragma unroll
      for (int dx = 0; dx < 5; dx++) {
        float pv = pp_[dy * 68 + dx];
        int k = dy * 5 + dx;
        a0 += mk[k] * pv;        // s=0 (s0=0,s1=0)
        a1 += mk[25 + k] * pv;   // s=1 (s0=0,s1=1)
        a2 += mk[50 + k] * pv;   // s=2 (s0=1,s1=0)
        a3 += mk[75 + k] * pv;   // s=3 (s0=1,s1=1)
      }
    }
    float* op = ob + (size_t)c * 128 * 128;
    *(float2*)op = make_float2(a0, a1);           // row 2i,   cols 2j,2j+1
    *(float2*)(op + 128) = make_float2(a2, a3);   // row 2i+1, cols 2j,2j+1
  }
}

// ---------------------------------------------------------------------------
extern "C" void kernel_launch(void* const* d_in, const int* in_sizes, int n_in,
                              void* d_out, int out_size) {
  const float* x   = (const float*)d_in[0];   // [4,256,64,64]
  const float* wc  = (const float*)d_in[1];   // [64,256]
  const float* gma = (const float*)d_in[2];   // [64]
  const float* bet = (const float*)d_in[3];   // [64]
  const float* mea = (const float*)d_in[4];   // [64]
  const float* var = (const float*)d_in[5];   // [64]
  const float* we  = (const float*)d_in[6];   // [100,64,3,3]
  float* out = (float*)d_out;                 // [4,256,128,128]

  int smA = (256 * 64 + 256 * 68) * 4;   // 135168
  int smB = (6400 + 14544) * 4;          // 83776
  int smC = 64 * 6 * 68 * 4;             // 104448
  cudaFuncSetAttribute(kA, cudaFuncAttributeMaxDynamicSharedMemorySize, smA);
  cudaFuncSetAttribute(kB, cudaFuncAttributeMaxDynamicSharedMemorySize, smB);
  cudaFuncSetAttribute(kC, cudaFuncAttributeMaxDynamicSharedMemorySize, smC);

  kA<<<256, 256, smA>>>(x, wc, gma, bet, mea, var);
  kB<<<dim3(8, 8, 4), 128, smB>>>(we);
  kC<<<dim3(4, 32, 4), 128, smC>>>(x, out);
}

// round 4
// speedup vs baseline: 1.5865x; 1.5865x over previous
#include <cuda_runtime.h>

#define HW 4096  // 64*64

// Device scratch (no allocation allowed in kernel_launch)
__device__ float g_act[4 * 64 * HW];          // [b][co=64][h][w], post BN+SiLU
__device__ float g_mask[4 * HW * 112];        // [b][pixel][s=4][28pad], softmaxed
__device__ float g_wt2[576 * 112];            // enc w: [t=ci*9+r][s][28pad]
__device__ float g_wct[256 * 64];             // comp w: [c][o]

// ---------------------------------------------------------------------------
// kW: one-time weight reorganization (runs inside the graph; ~2us)
// ---------------------------------------------------------------------------
__global__ void __launch_bounds__(256) kW(const float* __restrict__ wc,
                                          const float* __restrict__ we) {
  int idx = blockIdx.x * 256 + threadIdx.x;
  if (idx < 576 * 112) {
    int t = idx / 112;
    int rem = idx - t * 112;
    int s = rem / 28, k = rem - s * 28;
    g_wt2[idx] = (k < 25) ? we[(k * 4 + s) * 576 + t] : 0.f;
  }
  int j = idx - 576 * 112;
  if (j >= 0 && j < 256 * 64) {
    int c = j >> 6, o = j & 63;
    g_wct[j] = wc[o * 256 + c];
  }
}

// ---------------------------------------------------------------------------
// kA: 1x1 conv (256->64) + BN(eval) + SiLU.
// Block = 64 px x 64 out, 128 threads, thread tile 8 out x 4 px.
// smem 32KB (ci chunks of 64) -> high occupancy.
// ---------------------------------------------------------------------------
__global__ void __launch_bounds__(128) kA(
    const float* __restrict__ x,
    const float* __restrict__ gma, const float* __restrict__ bet,
    const float* __restrict__ mea, const float* __restrict__ var) {
  __shared__ float xs[64 * 64];
  __shared__ float ws[64 * 64];

  int blk = blockIdx.x;
  int b = blk >> 6;
  int p0 = (blk & 63) << 6;
  int tid = threadIdx.x;
  int pp = tid & 15;   // 4 pixels
  int po = tid >> 4;   // 8 outputs

  float acc[8][4] = {};
  const float* xb = x + (size_t)(b * 256) * HW + p0;

#pragma unroll 1
  for (int cc = 0; cc < 4; cc++) {
    __syncthreads();
    const float4* xg = (const float4*)(xb + (size_t)cc * 64 * HW);
    float4* xsd = (float4*)xs;
    for (int u = tid; u < 1024; u += 128) {
      int ci = u >> 4, m = u & 15;
      xsd[u] = xg[ci * 1024 + m];
    }
    const float4* wg = (const float4*)(g_wct + cc * 64 * 64);
    float4* wsd = (float4*)ws;
    for (int u = tid; u < 1024; u += 128) wsd[u] = wg[u];
    __syncthreads();

#pragma unroll 4
    for (int ci = 0; ci < 64; ci++) {
      float4 xv = *(const float4*)(xs + ci * 64 + pp * 4);
      float4 w0 = *(const float4*)(ws + ci * 64 + po * 8);
      float4 w1 = *(const float4*)(ws + ci * 64 + po * 8 + 4);
      float xa[4] = {xv.x, xv.y, xv.z, xv.w};
      float wa[8] = {w0.x, w0.y, w0.z, w0.w, w1.x, w1.y, w1.z, w1.w};
#pragma unroll
      for (int oo = 0; oo < 8; oo++)
#pragma unroll
        for (int pz = 0; pz < 4; pz++)
          acc[oo][pz] += wa[oo] * xa[pz];
    }
  }

  float* actb = g_act + (size_t)(b * 64) * HW + p0 + pp * 4;
#pragma unroll
  for (int oo = 0; oo < 8; oo++) {
    int o = po * 8 + oo;
    float inv = gma[o] * rsqrtf(var[o] + 1e-5f);
    float off = bet[o] - mea[o] * inv;
    float4 r;
    float v;
    v = acc[oo][0] * inv + off; r.x = v / (1.f + __expf(-v));
    v = acc[oo][1] * inv + off; r.y = v / (1.f + __expf(-v));
    v = acc[oo][2] * inv + off; r.z = v / (1.f + __expf(-v));
    v = acc[oo][3] * inv + off; r.w = v / (1.f + __expf(-v));
    *(float4*)(actb + (size_t)o * HW) = r;
  }
}

// ---------------------------------------------------------------------------
// kB: 3x3 conv (64->100ch, pad 1) + softmax over k (per s), per-thread.
// Block: 8x8 px tile, 128 threads = 32 slots x 4 s; 2 px/thread, 25 acc each.
// Weights from g_wt2 [t][s][28pad]: float4 register loads, broadcast reads.
// ci chunks of 4 -> smem 41.7KB -> 4+ blocks/SM.
// ---------------------------------------------------------------------------
__device__ __forceinline__ void softmax25_store(float* acc, float* dst) {
  float m = acc[0];
#pragma unroll
  for (int k = 1; k < 25; k++) m = fmaxf(m, acc[k]);
  float ssum = 0.f;
#pragma unroll
  for (int k = 0; k < 25; k++) { acc[k] = __expf(acc[k] - m); ssum += acc[k]; }
  float rs = 1.f / ssum;
#pragma unroll
  for (int t = 0; t < 6; t++)
    *(float4*)(dst + 4 * t) = make_float4(acc[4 * t] * rs, acc[4 * t + 1] * rs,
                                          acc[4 * t + 2] * rs, acc[4 * t + 3] * rs);
  dst[24] = acc[24] * rs;
}

__global__ void __launch_bounds__(128, 4) kB() {
  __shared__ float as_[6400];   // act tile [64][10][10]
  __shared__ float ws[4032];    // weight chunk [36][112]

  int b = blockIdx.z;
  int i0 = blockIdx.y << 3, j0 = blockIdx.x << 3;
  int tid = threadIdx.x;
  int s = tid & 3, q = tid >> 2;
  int ty = q >> 3, tx = q & 7;

  for (int idx = tid; idx < 6400; idx += 128) {
    int ci = idx / 100;
    int rem = idx - ci * 100;
    int rr = rem / 10, cc2 = rem - rr * 10;
    int gi = i0 + rr - 1, gj = j0 + cc2 - 1;
    float v = 0.f;
    if ((unsigned)gi < 64u && (unsigned)gj < 64u)
      v = g_act[((size_t)(b * 64 + ci)) * HW + (gi << 6) + gj];
    as_[idx] = v;
  }

  float acc0[25] = {}, acc1[25] = {};

#pragma unroll 1
  for (int cc = 0; cc < 16; cc++) {
    __syncthreads();
    const float4* src = (const float4*)(g_wt2 + cc * 4032);
    float4* dstw = (float4*)ws;
    for (int u = tid; u < 1008; u += 128) dstw[u] = src[u];
    __syncthreads();
#pragma unroll 1
    for (int cl = 0; cl < 4; cl++) {
      const float* ap = as_ + (cc * 4 + cl) * 100;
#pragma unroll
      for (int r = 0; r < 9; r++) {
        int dy = r / 3, dx = r - dy * 3;
        float a0 = ap[(ty + dy) * 10 + tx + dx];
        float a1 = ap[(ty + 4 + dy) * 10 + tx + dx];
        const float* wp = ws + (cl * 9 + r) * 112 + s * 28;
        float w[25];
#pragma unroll
        for (int t = 0; t < 6; t++) {
          float4 v = *(const float4*)(wp + 4 * t);
          w[4 * t] = v.x; w[4 * t + 1] = v.y; w[4 * t + 2] = v.z; w[4 * t + 3] = v.w;
        }
        w[24] = wp[24];
#pragma unroll
        for (int k = 0; k < 25; k++) {
          acc0[k] += w[k] * a0;
          acc1[k] += w[k] * a1;
        }
      }
    }
  }

  int p0 = (i0 + ty) * 64 + (j0 + tx);
  int p1 = p0 + 256;
  softmax25_store(acc0, g_mask + ((size_t)(b * HW + p0)) * 112 + s * 28);
  softmax25_store(acc1, g_mask + ((size_t)(b * HW + p1)) * 112 + s * 28);
}

// ---------------------------------------------------------------------------
// kC: 5x5 unfold + mask-weighted sum + pixel shuffle (x2).
// Block: (ch-chunk of 32, row pair, b). 128 threads = (r,j). Mask (100 vals)
// in registers, reused across 32 channels.
// ---------------------------------------------------------------------------
__global__ void __launch_bounds__(128, 3) kC(const float* __restrict__ x,
                                             float* __restrict__ out) {
  extern __shared__ float xs[];   // [32][6][68] = 13056 floats
  int gc0 = blockIdx.x << 5;
  int ri = blockIdx.y;
  int b = blockIdx.z;
  int tid = threadIdx.x;
  int r = tid >> 6, j = tid & 63;
  int i = (ri << 1) + r;

  const float* xb = x + ((size_t)(b * 256 + gc0)) * HW;
  for (int u = tid; u < 3072; u += 128) {
    int c = u / 96;
    int rem = u - c * 96;
    int lr = rem >> 4, m = rem & 15;
    int grow = (ri << 1) - 2 + lr;
    float4 v = make_float4(0.f, 0.f, 0.f, 0.f);
    if ((unsigned)grow < 64u)
      v = *(const float4*)(xb + (size_t)c * HW + (grow << 6) + m * 4);
    float* d = xs + c * 408 + lr * 68 + 2 + m * 4;
    *(float2*)d = make_float2(v.x, v.y);
    *(float2*)(d + 2) = make_float2(v.z, v.w);
  }
  // halo columns (0,1) and (66,67) = zero
  for (int u = tid; u < 384; u += 128) {
    int c = u / 12;
    int rem = u - c * 12;
    int lr = rem >> 1, side = rem & 1;
    *(float2*)(xs + c * 408 + lr * 68 + side * 66) = make_float2(0.f, 0.f);
  }
  __syncthreads();

  // Mask -> registers: mk[s*28 + k]
  float mk[112];
  const float4* mp =
      (const float4*)(g_mask + ((size_t)(b * HW + (i << 6) + j)) * 112);
#pragma unroll
  for (int t = 0; t < 28; t++) {
    float4 v = mp[t];
    mk[4 * t] = v.x; mk[4 * t + 1] = v.y; mk[4 * t + 2] = v.z; mk[4 * t + 3] = v.w;
  }

  const float* pbase = xs + r * 68 + j;
  float* ob = out + ((size_t)(b * 256 + gc0) * 128 + (i << 1)) * 128 + (j << 1);

#pragma unroll 1
  for (int c = 0; c < 32; c++) {
    const float* pq = pbase + c * 408;
    float a0 = 0.f, a1 = 0.f, a2 = 0.f, a3 = 0.f;
#pragma unroll
    for (int dy = 0; dy < 5; dy++) {
#pragma unroll
      for (int dx = 0; dx < 5; dx++) {
        float pv = pq[dy * 68 + dx];
        int k = dy * 5 + dx;
        a0 += mk[k] * pv;
        a1 += mk[28 + k] * pv;
        a2 += mk[56 + k] * pv;
        a3 += mk[84 + k] * pv;
      }
    }
    float* op = ob + (size_t)c * 128 * 128;
    *(float2*)op = make_float2(a0, a1);
    *(float2*)(op + 128) = make_float2(a2, a3);
  }
}

// ---------------------------------------------------------------------------
extern "C" void kernel_launch(void* const* d_in, const int* in_sizes, int n_in,
                              void* d_out, int out_size) {
  const float* x   = (const float*)d_in[0];
  const float* wc  = (const float*)d_in[1];
  const float* gma = (const float*)d_in[2];
  const float* bet = (const float*)d_in[3];
  const float* mea = (const float*)d_in[4];
  const float* var = (const float*)d_in[5];
  const float* we  = (const float*)d_in[6];
  float* out = (float*)d_out;

  int smC = 32 * 408 * 4;  // 52224
  cudaFuncSetAttribute(kC, cudaFuncAttributeMaxDynamicSharedMemorySize, smC);

  kW<<<(576 * 112 + 256 * 64 + 255) / 256, 256>>>(wc, we);
  kA<<<256, 128>>>(x, gma, bet, mea, var);
  kB<<<dim3(8, 8, 4), 128>>>();
  kC<<<dim3(8, 32, 4), 128, smC>>>(x, out);
}